// round 1
// baseline (speedup 1.0000x reference)
#include <cuda_runtime.h>
#include <math.h>

#define NTOK 4096
#define DIM  1024
#define NEXP 8
#define HID  2048
#define NPAIR (NTOK * 2)

// ---------------- scratch (static device memory; no allocations) -------------
__device__ int   g_cnt[NEXP];
__device__ int   g_list[NEXP * NTOK];   // pair slot p = n*2 + k
__device__ float g_pw[NPAIR];           // normalized top-2 weights per pair
__device__ float g_act[(size_t)NPAIR * HID]; // SwiGLU activations
__device__ float g_y[(size_t)NPAIR * DIM];   // per-pair expert outputs

// ---------------- init ------------------------------------------------------
__global__ void init_kernel() {
    if (threadIdx.x < NEXP) g_cnt[threadIdx.x] = 0;
}

// ---------------- router ----------------------------------------------------
// one warp per token; gate_w cached in smem
__global__ void router_kernel(const float* __restrict__ x,
                              const float* __restrict__ gw,
                              float* __restrict__ logits) {
    __shared__ float sgw[NEXP * DIM];   // 32 KB
    for (int i = threadIdx.x; i < NEXP * DIM; i += blockDim.x)
        sgw[i] = gw[i];
    __syncthreads();

    int warp = threadIdx.x >> 5;
    int lane = threadIdx.x & 31;
    int n = blockIdx.x * (blockDim.x >> 5) + warp;
    if (n >= NTOK) return;

    const float* xr = x + (size_t)n * DIM;
    float acc[NEXP];
#pragma unroll
    for (int e = 0; e < NEXP; e++) acc[e] = 0.f;

    for (int k = lane; k < DIM; k += 32) {
        float xv = xr[k];
#pragma unroll
        for (int e = 0; e < NEXP; e++) acc[e] += xv * sgw[e * DIM + k];
    }
#pragma unroll
    for (int e = 0; e < NEXP; e++) {
#pragma unroll
        for (int off = 16; off; off >>= 1)
            acc[e] += __shfl_xor_sync(0xffffffffu, acc[e], off);
    }

    if (lane == 0) {
        // top-2 by logits (softmax is monotone); first-index wins on ties
        int a = 0;
#pragma unroll
        for (int e = 1; e < NEXP; e++) if (acc[e] > acc[a]) a = e;
        int b = (a == 0) ? 1 : 0;
#pragma unroll
        for (int e = 0; e < NEXP; e++) {
            if (e == a || e == b) continue;
            if (acc[e] > acc[b]) b = e;
        }
        // normalized top-2 weights: softmax renorm cancels
        float eb = expf(acc[b] - acc[a]);
        float inv = 1.f / (1.f + eb);
        g_pw[n * 2 + 0] = inv;
        g_pw[n * 2 + 1] = eb * inv;

        int pa = atomicAdd(&g_cnt[a], 1);
        g_list[a * NTOK + pa] = n * 2 + 0;
        int pb = atomicAdd(&g_cnt[b], 1);
        g_list[b * NTOK + pb] = n * 2 + 1;

#pragma unroll
        for (int e = 0; e < NEXP; e++) logits[(size_t)n * NEXP + e] = acc[e];
    }
}

// ---------------- GEMM1: act = swiglu(x @ w1[e]) -----------------------------
// tile 128(rows) x 64(out cols, both g and lin halves) x 16(k), 256 threads,
// thread micro-tile 8x4 for each of g/lin.
#define G1_BM 128
#define G1_BN 64
#define G1_BK 16

__global__ __launch_bounds__(256)
void gemm1_kernel(const float* __restrict__ x, const float* __restrict__ w1) {
    int e = blockIdx.z;
    int cnt = g_cnt[e];
    int row0 = blockIdx.y * G1_BM;
    if (row0 >= cnt) return;
    int col0 = blockIdx.x * G1_BN;   // over HID

    __shared__ __align__(16) float As[G1_BK][G1_BM];
    __shared__ __align__(16) float Bg[G1_BK][G1_BN];
    __shared__ __align__(16) float Bl[G1_BK][G1_BN];
    __shared__ int sp[G1_BM];

    int tid = threadIdx.x;
    if (tid < G1_BM) {
        int r = row0 + tid;
        sp[tid] = g_list[e * NTOK + min(r, cnt - 1)];
    }
    __syncthreads();

    const float* w1e = w1 + (size_t)e * DIM * (2 * HID);

    // A-load mapping: thread -> row (tid>>1), 8 consecutive k (2 float4)
    int am = tid >> 1;
    int ak = (tid & 1) * 8;
    const float* xrow = x + (size_t)(sp[am] >> 1) * DIM;
    // B-load mapping
    int bk = tid >> 4;
    int bc = (tid & 15) * 4;
    const float* bgp = w1e + (size_t)bk * (2 * HID) + col0 + bc;
    const float* blp = bgp + HID;

    int tn = tid & 15;  // *4 cols
    int tm = tid >> 4;  // *8 rows

    float accg[8][4], accl[8][4];
#pragma unroll
    for (int i = 0; i < 8; i++)
#pragma unroll
        for (int j = 0; j < 4; j++) { accg[i][j] = 0.f; accl[i][j] = 0.f; }

    for (int k0 = 0; k0 < DIM; k0 += G1_BK) {
        float4 v0 = *(const float4*)(xrow + k0 + ak);
        float4 v1 = *(const float4*)(xrow + k0 + ak + 4);
        float4 bg = *(const float4*)(bgp + (size_t)k0 * (2 * HID));
        float4 bl = *(const float4*)(blp + (size_t)k0 * (2 * HID));
        __syncthreads();
        As[ak + 0][am] = v0.x; As[ak + 1][am] = v0.y;
        As[ak + 2][am] = v0.z; As[ak + 3][am] = v0.w;
        As[ak + 4][am] = v1.x; As[ak + 5][am] = v1.y;
        As[ak + 6][am] = v1.z; As[ak + 7][am] = v1.w;
        *(float4*)&Bg[bk][bc] = bg;
        *(float4*)&Bl[bk][bc] = bl;
        __syncthreads();

#pragma unroll
        for (int kk = 0; kk < G1_BK; kk++) {
            float a[8];
            *(float4*)&a[0] = *(const float4*)&As[kk][tm * 8];
            *(float4*)&a[4] = *(const float4*)&As[kk][tm * 8 + 4];
            float4 vg = *(const float4*)&Bg[kk][tn * 4];
            float4 vl = *(const float4*)&Bl[kk][tn * 4];
#pragma unroll
            for (int i = 0; i < 8; i++) {
                accg[i][0] += a[i] * vg.x; accg[i][1] += a[i] * vg.y;
                accg[i][2] += a[i] * vg.z; accg[i][3] += a[i] * vg.w;
                accl[i][0] += a[i] * vl.x; accl[i][1] += a[i] * vl.y;
                accl[i][2] += a[i] * vl.z; accl[i][3] += a[i] * vl.w;
            }
        }
    }

    // epilogue: SwiGLU, store to act scratch
#pragma unroll
    for (int i = 0; i < 8; i++) {
        int r = row0 + tm * 8 + i;
        if (r < cnt) {
            int p = sp[tm * 8 + i];
            float4 o;
            float g0 = accg[i][0], g1 = accg[i][1], g2 = accg[i][2], g3 = accg[i][3];
            o.x = (g0 / (1.f + expf(-g0))) * accl[i][0];
            o.y = (g1 / (1.f + expf(-g1))) * accl[i][1];
            o.z = (g2 / (1.f + expf(-g2))) * accl[i][2];
            o.w = (g3 / (1.f + expf(-g3))) * accl[i][3];
            *(float4*)(g_act + (size_t)p * HID + col0 + tn * 4) = o;
        }
    }
}

// ---------------- GEMM2: y = act @ w2[e] -------------------------------------
// tile 128x128x8, 256 threads, 8x8 micro-tile
#define G2_BM 128
#define G2_BN 128
#define G2_BK 8

__global__ __launch_bounds__(256)
void gemm2_kernel(const float* __restrict__ w2) {
    int e = blockIdx.z;
    int cnt = g_cnt[e];
    int row0 = blockIdx.y * G2_BM;
    if (row0 >= cnt) return;
    int col0 = blockIdx.x * G2_BN;   // over DIM

    __shared__ __align__(16) float As[G2_BK][G2_BM];
    __shared__ __align__(16) float Bs[G2_BK][G2_BN];
    __shared__ int sp[G2_BM];

    int tid = threadIdx.x;
    if (tid < G2_BM) {
        int r = row0 + tid;
        sp[tid] = g_list[e * NTOK + min(r, cnt - 1)];
    }
    __syncthreads();

    const float* w2e = w2 + (size_t)e * HID * DIM;

    int am = tid >> 1;
    int ak = (tid & 1) * 4;
    const float* arow = g_act + (size_t)sp[am] * HID;
    int bk = tid >> 5;
    int bc = (tid & 31) * 4;
    const float* bp = w2e + (size_t)bk * DIM + col0 + bc;

    int tn = tid & 15;  // *8 cols
    int tm = tid >> 4;  // *8 rows

    float acc[8][8];
#pragma unroll
    for (int i = 0; i < 8; i++)
#pragma unroll
        for (int j = 0; j < 8; j++) acc[i][j] = 0.f;

    for (int k0 = 0; k0 < HID; k0 += G2_BK) {
        float4 va = *(const float4*)(arow + k0 + ak);
        float4 vb = *(const float4*)(bp + (size_t)k0 * DIM);
        __syncthreads();
        As[ak + 0][am] = va.x; As[ak + 1][am] = va.y;
        As[ak + 2][am] = va.z; As[ak + 3][am] = va.w;
        *(float4*)&Bs[bk][bc] = vb;
        __syncthreads();

#pragma unroll
        for (int kk = 0; kk < G2_BK; kk++) {
            float a[8], b[8];
            *(float4*)&a[0] = *(const float4*)&As[kk][tm * 8];
            *(float4*)&a[4] = *(const float4*)&As[kk][tm * 8 + 4];
            *(float4*)&b[0] = *(const float4*)&Bs[kk][tn * 8];
            *(float4*)&b[4] = *(const float4*)&Bs[kk][tn * 8 + 4];
#pragma unroll
            for (int i = 0; i < 8; i++)
#pragma unroll
                for (int j = 0; j < 8; j++)
                    acc[i][j] += a[i] * b[j];
        }
    }

#pragma unroll
    for (int i = 0; i < 8; i++) {
        int r = row0 + tm * 8 + i;
        if (r < cnt) {
            int p = sp[tm * 8 + i];
            float* yp = g_y + (size_t)p * DIM + col0 + tn * 8;
            float4 o0, o1;
            o0.x = acc[i][0]; o0.y = acc[i][1]; o0.z = acc[i][2]; o0.w = acc[i][3];
            o1.x = acc[i][4]; o1.y = acc[i][5]; o1.z = acc[i][6]; o1.w = acc[i][7];
            *(float4*)(yp + 0) = o0;
            *(float4*)(yp + 4) = o1;
        }
    }
}

// ---------------- combine ----------------------------------------------------
__global__ void combine_kernel(float* __restrict__ out) {
    int i = blockIdx.x * blockDim.x + threadIdx.x;   // over NTOK*DIM/4
    if (i >= NTOK * DIM / 4) return;
    int n  = i / (DIM / 4);
    int c4 = (i % (DIM / 4)) * 4;
    float w0 = g_pw[2 * n];
    float w1 = g_pw[2 * n + 1];
    float4 y0 = *(const float4*)(g_y + (size_t)(2 * n) * DIM + c4);
    float4 y1 = *(const float4*)(g_y + (size_t)(2 * n + 1) * DIM + c4);
    float4 o;
    o.x = w0 * y0.x + w1 * y1.x;
    o.y = w0 * y0.y + w1 * y1.y;
    o.z = w0 * y0.z + w1 * y1.z;
    o.w = w0 * y0.w + w1 * y1.w;
    *(float4*)(out + (size_t)n * DIM + c4) = o;
}

// ---------------- launch -----------------------------------------------------
extern "C" void kernel_launch(void* const* d_in, const int* in_sizes, int n_in,
                              void* d_out, int out_size) {
    const float* x  = (const float*)d_in[0];   // [2,2048,1024]
    const float* gw = (const float*)d_in[1];   // [8,1024]
    const float* w1 = (const float*)d_in[2];   // [8,1024,4096]
    const float* w2 = (const float*)d_in[3];   // [8,2048,1024]
    float* out    = (float*)d_out;                    // [2,2048,1024]
    float* logits = out + (size_t)NTOK * DIM;         // [2,2048,8]

    init_kernel<<<1, 32>>>();
    router_kernel<<<NTOK / 8, 256>>>(x, gw, logits);

    dim3 g1(HID / G1_BN, NTOK / G1_BM, NEXP);   // (32, 32, 8)
    gemm1_kernel<<<g1, 256>>>(x, w1);

    dim3 g2(DIM / G2_BN, NTOK / G2_BM, NEXP);   // (8, 32, 8)
    gemm2_kernel<<<g2, 256>>>(w2);

    combine_kernel<<<(NTOK * DIM / 4 + 255) / 256, 256>>>(out);
}

// round 3
// speedup vs baseline: 2.2065x; 2.2065x over previous
#include <cuda_runtime.h>
#include <cuda_bf16.h>
#include <math.h>
#include <stdint.h>

#define NTOK 4096
#define DIM  1024
#define NEXP 8
#define HID  2048
#define NPAIR (NTOK * 2)
#define K1 (3 * DIM)    // 3072  A:[hi|lo|hi]  B:[hi|hi|lo]
#define K2 (3 * HID)    // 6144

// ---------------- scratch ----------------------------------------------------
__device__ int   g_cnt[NEXP];
__device__ int   g_list[NEXP * NTOK];
__device__ float g_pw[NPAIR];
__device__ __nv_bfloat16 g_xb [(size_t)NTOK * K1];
__device__ __nv_bfloat16 g_w1b[(size_t)NEXP * 2 * HID * K1];
__device__ __nv_bfloat16 g_w2b[(size_t)NEXP * DIM * K2];
__device__ __nv_bfloat16 g_actb[(size_t)NPAIR * K2];
__device__ float g_y[(size_t)NPAIR * DIM];

// ---------------- helpers ----------------------------------------------------
__device__ __forceinline__ uint32_t smem_u32(const void* p) {
    uint32_t a;
    asm("{ .reg .u64 t; cvta.to.shared.u64 t, %1; cvt.u32.u64 %0, t; }" : "=r"(a) : "l"(p));
    return a;
}
__device__ __forceinline__ uint32_t lds32(uint32_t a) {
    uint32_t v;
    asm("ld.shared.b32 %0, [%1];" : "=r"(v) : "r"(a));
    return v;
}
__device__ __forceinline__ void mma16816(float* c, const uint32_t* a, uint32_t b0, uint32_t b1) {
    asm volatile("mma.sync.aligned.m16n8k16.row.col.f32.bf16.bf16.f32 "
        "{%0,%1,%2,%3}, {%4,%5,%6,%7}, {%8,%9}, {%0,%1,%2,%3};"
        : "+f"(c[0]), "+f"(c[1]), "+f"(c[2]), "+f"(c[3])
        : "r"(a[0]), "r"(a[1]), "r"(a[2]), "r"(a[3]), "r"(b0), "r"(b1));
}
#define SWZ(o) ((o) ^ (((o) >> 3) & 0x70))
#define CP16(dst, src) asm volatile("cp.async.cg.shared.global [%0], [%1], 16;" :: "r"(dst), "l"(src))
#define CP_COMMIT() asm volatile("cp.async.commit_group;")
#define CP_WAIT1()  asm volatile("cp.async.wait_group 1;")
#define CP_WAIT0()  asm volatile("cp.async.wait_group 0;")

// smem map (relative to 1024-aligned base): [0,512) sp ; buffers at +1024:
//  A0 +1024, B0 +17408, A1 +33792, B1 +50176 (each 16KB) ; epilogue Sacc at +1024
#define SMEM_BYTES 68096

// ---------------- init / router ----------------------------------------------
__global__ void init_kernel() {
    if (threadIdx.x < NEXP) g_cnt[threadIdx.x] = 0;
}

__global__ void router_kernel(const float* __restrict__ x,
                              const float* __restrict__ gw,
                              float* __restrict__ logits) {
    __shared__ float sgw[NEXP * DIM];
    for (int i = threadIdx.x; i < NEXP * DIM; i += blockDim.x) sgw[i] = gw[i];
    __syncthreads();
    int warp = threadIdx.x >> 5, lane = threadIdx.x & 31;
    int n = blockIdx.x * (blockDim.x >> 5) + warp;
    if (n >= NTOK) return;
    const float* xr = x + (size_t)n * DIM;
    float acc[NEXP];
#pragma unroll
    for (int e = 0; e < NEXP; e++) acc[e] = 0.f;
    for (int k = lane; k < DIM; k += 32) {
        float xv = xr[k];
#pragma unroll
        for (int e = 0; e < NEXP; e++) acc[e] += xv * sgw[e * DIM + k];
    }
#pragma unroll
    for (int e = 0; e < NEXP; e++)
#pragma unroll
        for (int off = 16; off; off >>= 1)
            acc[e] += __shfl_xor_sync(0xffffffffu, acc[e], off);
    if (lane == 0) {
        int a = 0;
#pragma unroll
        for (int e = 1; e < NEXP; e++) if (acc[e] > acc[a]) a = e;
        int b = (a == 0) ? 1 : 0;
#pragma unroll
        for (int e = 0; e < NEXP; e++) {
            if (e == a || e == b) continue;
            if (acc[e] > acc[b]) b = e;
        }
        float eb = expf(acc[b] - acc[a]);
        float inv = 1.f / (1.f + eb);
        g_pw[n * 2 + 0] = inv;
        g_pw[n * 2 + 1] = eb * inv;
        int pa = atomicAdd(&g_cnt[a], 1); g_list[a * NTOK + pa] = n * 2 + 0;
        int pb = atomicAdd(&g_cnt[b], 1); g_list[b * NTOK + pb] = n * 2 + 1;
#pragma unroll
        for (int e = 0; e < NEXP; e++) logits[(size_t)n * NEXP + e] = acc[e];
    }
}

// ---------------- conversions ------------------------------------------------
__device__ __forceinline__ void split_bf16(float v, __nv_bfloat16& hi, __nv_bfloat16& lo) {
    hi = __float2bfloat16(v);
    lo = __float2bfloat16(v - __bfloat162float(hi));
}

__global__ void convert_x_kernel(const float* __restrict__ x) {
    int i = blockIdx.x * blockDim.x + threadIdx.x;
    if (i >= NTOK * DIM / 4) return;
    int n = i >> 8;
    int k = (i & 255) * 4;
    float4 v = *(const float4*)(x + (size_t)n * DIM + k);
    __nv_bfloat16 h[4], l[4];
    split_bf16(v.x, h[0], l[0]); split_bf16(v.y, h[1], l[1]);
    split_bf16(v.z, h[2], l[2]); split_bf16(v.w, h[3], l[3]);
    __nv_bfloat16* o = g_xb + (size_t)n * K1 + k;
#pragma unroll
    for (int j = 0; j < 4; j++) {
        o[j] = h[j]; o[DIM + j] = l[j]; o[2 * DIM + j] = h[j];
    }
}

__global__ void convert_w1_kernel(const float* __restrict__ w1) {
    __shared__ float t[32][33];
    int e = blockIdx.z, n0 = blockIdx.x * 32, k0 = blockIdx.y * 32;
    int tx = threadIdx.x, ty = threadIdx.y;
    const float* src = w1 + (size_t)e * DIM * (2 * HID);
#pragma unroll
    for (int j = 0; j < 4; j++) {
        int kk = ty + j * 8;
        t[kk][tx] = src[(size_t)(k0 + kk) * (2 * HID) + n0 + tx];
    }
    __syncthreads();
#pragma unroll
    for (int j = 0; j < 4; j++) {
        int nn = ty + j * 8;
        float v = t[tx][nn];
        __nv_bfloat16 hi, lo; split_bf16(v, hi, lo);
        size_t ob = ((size_t)e * (2 * HID) + n0 + nn) * K1 + k0 + tx;
        g_w1b[ob] = hi; g_w1b[ob + DIM] = hi; g_w1b[ob + 2 * DIM] = lo;
    }
}

__global__ void convert_w2_kernel(const float* __restrict__ w2) {
    __shared__ float t[32][33];
    int e = blockIdx.z, n0 = blockIdx.x * 32, k0 = blockIdx.y * 32;
    int tx = threadIdx.x, ty = threadIdx.y;
    const float* src = w2 + (size_t)e * HID * DIM;
#pragma unroll
    for (int j = 0; j < 4; j++) {
        int kk = ty + j * 8;
        t[kk][tx] = src[(size_t)(k0 + kk) * DIM + n0 + tx];
    }
    __syncthreads();
#pragma unroll
    for (int j = 0; j < 4; j++) {
        int nn = ty + j * 8;
        float v = t[tx][nn];
        __nv_bfloat16 hi, lo; split_bf16(v, hi, lo);
        size_t ob = ((size_t)e * DIM + n0 + nn) * K2 + k0 + tx;
        g_w2b[ob] = hi; g_w2b[ob + HID] = hi; g_w2b[ob + 2 * HID] = lo;
    }
}

// ---------------- mma.sync grouped GEMMs -------------------------------------
// Common per-chunk tile: A 128 rows x 64 k (bf16, SW128), B same. 256 threads.
// warp grid 4(m) x 2(n); warp tile 32x64 via m16n8k16 (2 m-tiles x 8 n-tiles).

#define LOADT(c, s) do {                                                      \
    const char* _ab = (const char*)Ag;                                        \
    const char* _bb = (const char*)Bg;                                        \
    _Pragma("unroll") for (int i = 0; i < 4; i++)                             \
        CP16(Ab_[s] + dst[i], _ab + aoff[i] + (size_t)(c) * 128);             \
    _Pragma("unroll") for (int i = 0; i < 4; i++)                             \
        CP16(Bb_[s] + dst[i], _bb + boff[i] + (size_t)(c) * 128);             \
    CP_COMMIT(); } while (0)

__global__ __launch_bounds__(256)
void gemm1_mma() {
    int e = blockIdx.z;
    int cnt = g_cnt[e];
    int row0 = blockIdx.y * 128;
    if (row0 >= cnt) return;
    int hcol0 = blockIdx.x * 64;

    extern __shared__ char sm[];
    uint32_t raw = smem_u32(sm);
    uint32_t base = (raw + 1023u) & ~1023u;
    char* smc = sm + (base - raw);
    int* sp = (int*)smc;
    uint32_t Ab_[2] = { base + 1024, base + 33792 };
    uint32_t Bb_[2] = { base + 17408, base + 50176 };

    int tid = threadIdx.x;
    if (tid < 128) sp[tid] = g_list[e * NTOK + min(row0 + tid, cnt - 1)];
    __syncthreads();

    // ---- loader mapping: 256 threads, 4 (row,seg) 16B pieces per tile each
    int seg = tid & 7, r0t = tid >> 3;
    const __nv_bfloat16* Ag = g_xb;
    const __nv_bfloat16* Bg = g_w1b + (size_t)e * (2 * HID) * K1;
    uint32_t dst[4], aoff[4], boff[4];
#pragma unroll
    for (int i = 0; i < 4; i++) {
        int r = r0t + 32 * i;
        dst[i] = SWZ(r * 128 + seg * 16);
        int tok = sp[r] >> 1;
        aoff[i] = (uint32_t)((size_t)tok * K1 * 2 + seg * 16);
        int nrow = (r < 64) ? (hcol0 + r) : (HID + hcol0 + (r - 64));
        boff[i] = (uint32_t)((size_t)nrow * K1 * 2 + seg * 16);
    }

    int l = tid & 31, wid = tid >> 5;
    int mw = (wid >> 1) * 32, nw = (wid & 1) * 64;
    uint32_t xm = ((uint32_t)(l >> 2)) << 4;
    uint32_t cb = (l & 3) * 4;

    float acc[2][8][4];
#pragma unroll
    for (int a = 0; a < 2; a++)
#pragma unroll
        for (int b = 0; b < 8; b++)
#pragma unroll
            for (int q = 0; q < 4; q++) acc[a][b][q] = 0.f;

    const int NC = K1 / 64;   // 48
    LOADT(0, 0);
    LOADT(1, 1);

    for (int c = 0; c < NC; c++) {
        int s = c & 1;
        if (c == NC - 1) CP_WAIT0(); else CP_WAIT1();
        __syncthreads();
        uint32_t arow = Ab_[s] + (mw + (l >> 2)) * 128;
        uint32_t brow = Bb_[s] + (nw + (l >> 2)) * 128;
#pragma unroll
        for (int ks = 0; ks < 4; ks++) {
            uint32_t kx0 = ((uint32_t)(ks * 32) + cb) ^ xm;
            uint32_t kx1 = kx0 ^ 16u;
            uint32_t a[2][4];
#pragma unroll
            for (int mt = 0; mt < 2; mt++) {
                uint32_t rb = arow + mt * 2048;
                a[mt][0] = lds32(rb + kx0);
                a[mt][1] = lds32(rb + 1024 + kx0);
                a[mt][2] = lds32(rb + kx1);
                a[mt][3] = lds32(rb + 1024 + kx1);
            }
#pragma unroll
            for (int j = 0; j < 8; j++) {
                uint32_t rb = brow + j * 1024;
                uint32_t b0 = lds32(rb + kx0);
                uint32_t b1 = lds32(rb + kx1);
                mma16816(acc[0][j], a[0], b0, b1);
                mma16816(acc[1][j], a[1], b0, b1);
            }
        }
        __syncthreads();
        if (c + 2 < NC) LOADT(c + 2, s);
    }

    // ---- epilogue: acc -> smem (stride 129) -> SwiGLU -> g_actb
    float* S = (float*)(smc + 1024);
#pragma unroll
    for (int mt = 0; mt < 2; mt++) {
        int rA = mw + mt * 16 + (l >> 2);
#pragma unroll
        for (int j = 0; j < 8; j++) {
            int cN = nw + j * 8 + (l & 3) * 2;
            S[rA * 129 + cN]     = acc[mt][j][0];
            S[rA * 129 + cN + 1] = acc[mt][j][1];
            S[(rA + 8) * 129 + cN]     = acc[mt][j][2];
            S[(rA + 8) * 129 + cN + 1] = acc[mt][j][3];
        }
    }
    __syncthreads();
#pragma unroll
    for (int pass = 0; pass < 16; pass++) {
        int m = pass * 8 + wid;
        int r = row0 + m;
        if (r < cnt) {
            int p = sp[m];
            __nv_bfloat16* ab = g_actb + (size_t)p * K2;
#pragma unroll
            for (int u = 0; u < 2; u++) {
                int hh = l + u * 32;
                float gv = S[m * 129 + hh];
                float lv = S[m * 129 + 64 + hh];
                float v = (gv / (1.f + expf(-gv))) * lv;
                __nv_bfloat16 hi, lo; split_bf16(v, hi, lo);
                int h = hcol0 + hh;
                ab[h] = hi; ab[HID + h] = lo; ab[2 * HID + h] = hi;
            }
        }
    }
}

__global__ __launch_bounds__(256)
void gemm2_mma() {
    int e = blockIdx.z;
    int cnt = g_cnt[e];
    int row0 = blockIdx.y * 128;
    if (row0 >= cnt) return;
    int n0 = blockIdx.x * 128;

    extern __shared__ char sm[];
    uint32_t raw = smem_u32(sm);
    uint32_t base = (raw + 1023u) & ~1023u;
    char* smc = sm + (base - raw);
    int* sp = (int*)smc;
    uint32_t Ab_[2] = { base + 1024, base + 33792 };
    uint32_t Bb_[2] = { base + 17408, base + 50176 };

    int tid = threadIdx.x;
    if (tid < 128) sp[tid] = g_list[e * NTOK + min(row0 + tid, cnt - 1)];
    __syncthreads();

    int seg = tid & 7, r0t = tid >> 3;
    const __nv_bfloat16* Ag = g_actb;
    const __nv_bfloat16* Bg = g_w2b + (size_t)e * DIM * K2;
    uint32_t dst[4], aoff[4], boff[4];
#pragma unroll
    for (int i = 0; i < 4; i++) {
        int r = r0t + 32 * i;
        dst[i] = SWZ(r * 128 + seg * 16);
        int p = sp[r];
        aoff[i] = (uint32_t)((size_t)p * K2 * 2 + seg * 16);
        boff[i] = (uint32_t)((size_t)(n0 + r) * K2 * 2 + seg * 16);
    }

    int l = tid & 31, wid = tid >> 5;
    int mw = (wid >> 1) * 32, nw = (wid & 1) * 64;
    uint32_t xm = ((uint32_t)(l >> 2)) << 4;
    uint32_t cb = (l & 3) * 4;

    float acc[2][8][4];
#pragma unroll
    for (int a = 0; a < 2; a++)
#pragma unroll
        for (int b = 0; b < 8; b++)
#pragma unroll
            for (int q = 0; q < 4; q++) acc[a][b][q] = 0.f;

    const int NC = K2 / 64;   // 96
    LOADT(0, 0);
    LOADT(1, 1);

    for (int c = 0; c < NC; c++) {
        int s = c & 1;
        if (c == NC - 1) CP_WAIT0(); else CP_WAIT1();
        __syncthreads();
        uint32_t arow = Ab_[s] + (mw + (l >> 2)) * 128;
        uint32_t brow = Bb_[s] + (nw + (l >> 2)) * 128;
#pragma unroll
        for (int ks = 0; ks < 4; ks++) {
            uint32_t kx0 = ((uint32_t)(ks * 32) + cb) ^ xm;
            uint32_t kx1 = kx0 ^ 16u;
            uint32_t a[2][4];
#pragma unroll
            for (int mt = 0; mt < 2; mt++) {
                uint32_t rb = arow + mt * 2048;
                a[mt][0] = lds32(rb + kx0);
                a[mt][1] = lds32(rb + 1024 + kx0);
                a[mt][2] = lds32(rb + kx1);
                a[mt][3] = lds32(rb + 1024 + kx1);
            }
#pragma unroll
            for (int j = 0; j < 8; j++) {
                uint32_t rb = brow + j * 1024;
                uint32_t b0 = lds32(rb + kx0);
                uint32_t b1 = lds32(rb + kx1);
                mma16816(acc[0][j], a[0], b0, b1);
                mma16816(acc[1][j], a[1], b0, b1);
            }
        }
        __syncthreads();
        if (c + 2 < NC) LOADT(c + 2, s);
    }

    // ---- epilogue: fragments straight to g_y
#pragma unroll
    for (int mt = 0; mt < 2; mt++) {
        int mloc = mw + mt * 16 + (l >> 2);
#pragma unroll
        for (int half = 0; half < 2; half++) {
            int m = mloc + half * 8;
            int r = row0 + m;
            if (r < cnt) {
                int p = sp[m];
                float* yp = g_y + (size_t)p * DIM + n0 + nw + (l & 3) * 2;
#pragma unroll
                for (int j = 0; j < 8; j++) {
                    float2 v;
                    v.x = acc[mt][j][half * 2 + 0];
                    v.y = acc[mt][j][half * 2 + 1];
                    *(float2*)(yp + j * 8) = v;
                }
            }
        }
    }
}

// ---------------- combine ----------------------------------------------------
__global__ void combine_kernel(float* __restrict__ out) {
    int i = blockIdx.x * blockDim.x + threadIdx.x;
    if (i >= NTOK * DIM / 4) return;
    int n  = i / (DIM / 4);
    int c4 = (i % (DIM / 4)) * 4;
    float w0 = g_pw[2 * n];
    float w1 = g_pw[2 * n + 1];
    float4 y0 = *(const float4*)(g_y + (size_t)(2 * n) * DIM + c4);
    float4 y1 = *(const float4*)(g_y + (size_t)(2 * n + 1) * DIM + c4);
    float4 o;
    o.x = w0 * y0.x + w1 * y1.x;
    o.y = w0 * y0.y + w1 * y1.y;
    o.z = w0 * y0.z + w1 * y1.z;
    o.w = w0 * y0.w + w1 * y1.w;
    *(float4*)(out + (size_t)n * DIM + c4) = o;
}

// ---------------- launch -----------------------------------------------------
extern "C" void kernel_launch(void* const* d_in, const int* in_sizes, int n_in,
                              void* d_out, int out_size) {
    const float* x  = (const float*)d_in[0];
    const float* gw = (const float*)d_in[1];
    const float* w1 = (const float*)d_in[2];
    const float* w2 = (const float*)d_in[3];
    float* out    = (float*)d_out;
    float* logits = out + (size_t)NTOK * DIM;

    cudaFuncSetAttribute(gemm1_mma, cudaFuncAttributeMaxDynamicSharedMemorySize, SMEM_BYTES);
    cudaFuncSetAttribute(gemm2_mma, cudaFuncAttributeMaxDynamicSharedMemorySize, SMEM_BYTES);

    init_kernel<<<1, 32>>>();
    router_kernel<<<NTOK / 8, 256>>>(x, gw, logits);

    convert_x_kernel<<<(NTOK * DIM / 4 + 255) / 256, 256>>>(x);
    convert_w1_kernel<<<dim3(2 * HID / 32, DIM / 32, NEXP), dim3(32, 8)>>>(w1);
    convert_w2_kernel<<<dim3(DIM / 32, HID / 32, NEXP), dim3(32, 8)>>>(w2);

    gemm1_mma<<<dim3(HID / 64, NTOK / 128, NEXP), 256, SMEM_BYTES>>>();
    gemm2_mma<<<dim3(DIM / 128, NTOK / 128, NEXP), 256, SMEM_BYTES>>>();

    combine_kernel<<<(NTOK * DIM / 4 + 255) / 256, 256>>>(out);
}

// round 4
// speedup vs baseline: 2.3378x; 1.0595x over previous
#include <cuda_runtime.h>
#include <cuda_bf16.h>
#include <math.h>
#include <stdint.h>

#define NTOK 4096
#define DIM  1024
#define NEXP 8
#define HID  2048
#define NPAIR (NTOK * 2)
// dedup storage: A-side [hi|lo], B-side [hi|lo]; logical K = 3x base
#define K1D (2 * DIM)    // 2048 elems, 4096 B rows (gemm1 operands)
#define K2D (2 * HID)    // 4096 elems, 8192 B rows (gemm2 operands)

// ---------------- scratch ----------------------------------------------------
__device__ int   g_cnt[NEXP];
__device__ int   g_list[NEXP * NTOK];
__device__ float g_pw[NPAIR];
__device__ __nv_bfloat16 g_xb [(size_t)NTOK * K1D];                  // 16 MB
__device__ __nv_bfloat16 g_w1b[(size_t)NEXP * 2 * HID * K1D];        // 134 MB
__device__ __nv_bfloat16 g_w2b[(size_t)NEXP * DIM * K2D];            // 67 MB
__device__ __nv_bfloat16 g_actb[(size_t)NPAIR * K2D];                // 67 MB
__device__ float g_y[(size_t)NPAIR * DIM];                           // 33 MB

// ---------------- helpers ----------------------------------------------------
__device__ __forceinline__ uint32_t smem_u32(const void* p) {
    uint32_t a;
    asm("{ .reg .u64 t; cvta.to.shared.u64 t, %1; cvt.u32.u64 %0, t; }" : "=r"(a) : "l"(p));
    return a;
}
__device__ __forceinline__ void ldsm4(uint32_t* r, uint32_t addr) {
    asm volatile("ldmatrix.sync.aligned.m8n8.x4.shared.b16 {%0,%1,%2,%3}, [%4];"
        : "=r"(r[0]), "=r"(r[1]), "=r"(r[2]), "=r"(r[3]) : "r"(addr));
}
__device__ __forceinline__ void mma16816(float* c, const uint32_t* a, uint32_t b0, uint32_t b1) {
    asm volatile("mma.sync.aligned.m16n8k16.row.col.f32.bf16.bf16.f32 "
        "{%0,%1,%2,%3}, {%4,%5,%6,%7}, {%8,%9}, {%0,%1,%2,%3};"
        : "+f"(c[0]), "+f"(c[1]), "+f"(c[2]), "+f"(c[3])
        : "r"(a[0]), "r"(a[1]), "r"(a[2]), "r"(a[3]), "r"(b0), "r"(b1));
}
#define SWZ(o) ((o) ^ (((o) >> 3) & 0x70))
#define CP16(dst, src) asm volatile("cp.async.cg.shared.global [%0], [%1], 16;" :: "r"(dst), "l"(src))
#define CP_COMMIT() asm volatile("cp.async.commit_group;")
#define CP_WAIT1()  asm volatile("cp.async.wait_group 1;")
#define CP_WAIT0()  asm volatile("cp.async.wait_group 0;")

// smem: base 1024-aligned; sp[128] @ +0; 3 stages: A @ 1024+s*32768, B = A+16384
#define SMEM_BYTES 100352

// ---------------- init / router ----------------------------------------------
__global__ void init_kernel() {
    if (threadIdx.x < NEXP) g_cnt[threadIdx.x] = 0;
}

__global__ void router_kernel(const float* __restrict__ x,
                              const float* __restrict__ gw,
                              float* __restrict__ logits) {
    __shared__ float sgw[NEXP * DIM];
    for (int i = threadIdx.x; i < NEXP * DIM; i += blockDim.x) sgw[i] = gw[i];
    __syncthreads();
    int warp = threadIdx.x >> 5, lane = threadIdx.x & 31;
    int n = blockIdx.x * (blockDim.x >> 5) + warp;
    if (n >= NTOK) return;
    const float* xr = x + (size_t)n * DIM;
    float acc[NEXP];
#pragma unroll
    for (int e = 0; e < NEXP; e++) acc[e] = 0.f;
    for (int k = lane; k < DIM; k += 32) {
        float xv = xr[k];
#pragma unroll
        for (int e = 0; e < NEXP; e++) acc[e] += xv * sgw[e * DIM + k];
    }
#pragma unroll
    for (int e = 0; e < NEXP; e++)
#pragma unroll
        for (int off = 16; off; off >>= 1)
            acc[e] += __shfl_xor_sync(0xffffffffu, acc[e], off);
    if (lane == 0) {
        int a = 0;
#pragma unroll
        for (int e = 1; e < NEXP; e++) if (acc[e] > acc[a]) a = e;
        int b = (a == 0) ? 1 : 0;
#pragma unroll
        for (int e = 0; e < NEXP; e++) {
            if (e == a || e == b) continue;
            if (acc[e] > acc[b]) b = e;
        }
        float eb = expf(acc[b] - acc[a]);
        float inv = 1.f / (1.f + eb);
        g_pw[n * 2 + 0] = inv;
        g_pw[n * 2 + 1] = eb * inv;
        int pa = atomicAdd(&g_cnt[a], 1); g_list[a * NTOK + pa] = n * 2 + 0;
        int pb = atomicAdd(&g_cnt[b], 1); g_list[b * NTOK + pb] = n * 2 + 1;
#pragma unroll
        for (int e = 0; e < NEXP; e++) logits[(size_t)n * NEXP + e] = acc[e];
    }
}

// ---------------- conversions (hi/lo split, dedup layout) ---------------------
__device__ __forceinline__ void split_bf16(float v, __nv_bfloat16& hi, __nv_bfloat16& lo) {
    hi = __float2bfloat16(v);
    lo = __float2bfloat16(v - __bfloat162float(hi));
}

__global__ void convert_x_kernel(const float* __restrict__ x) {
    int i = blockIdx.x * blockDim.x + threadIdx.x;
    if (i >= NTOK * DIM / 4) return;
    int n = i >> 8;
    int k = (i & 255) * 4;
    float4 v = *(const float4*)(x + (size_t)n * DIM + k);
    __nv_bfloat16 h[4], l[4];
    split_bf16(v.x, h[0], l[0]); split_bf16(v.y, h[1], l[1]);
    split_bf16(v.z, h[2], l[2]); split_bf16(v.w, h[3], l[3]);
    __nv_bfloat16* o = g_xb + (size_t)n * K1D + k;
#pragma unroll
    for (int j = 0; j < 4; j++) { o[j] = h[j]; o[DIM + j] = l[j]; }
}

__global__ void convert_w1_kernel(const float* __restrict__ w1) {
    __shared__ float t[32][33];
    int e = blockIdx.z, n0 = blockIdx.x * 32, k0 = blockIdx.y * 32;
    int tx = threadIdx.x, ty = threadIdx.y;
    const float* src = w1 + (size_t)e * DIM * (2 * HID);
#pragma unroll
    for (int j = 0; j < 4; j++) {
        int kk = ty + j * 8;
        t[kk][tx] = src[(size_t)(k0 + kk) * (2 * HID) + n0 + tx];
    }
    __syncthreads();
#pragma unroll
    for (int j = 0; j < 4; j++) {
        int nn = ty + j * 8;
        float v = t[tx][nn];
        __nv_bfloat16 hi, lo; split_bf16(v, hi, lo);
        size_t ob = ((size_t)e * (2 * HID) + n0 + nn) * K1D + k0 + tx;
        g_w1b[ob] = hi; g_w1b[ob + DIM] = lo;
    }
}

__global__ void convert_w2_kernel(const float* __restrict__ w2) {
    __shared__ float t[32][33];
    int e = blockIdx.z, n0 = blockIdx.x * 32, k0 = blockIdx.y * 32;
    int tx = threadIdx.x, ty = threadIdx.y;
    const float* src = w2 + (size_t)e * HID * DIM;
#pragma unroll
    for (int j = 0; j < 4; j++) {
        int kk = ty + j * 8;
        t[kk][tx] = src[(size_t)(k0 + kk) * DIM + n0 + tx];
    }
    __syncthreads();
#pragma unroll
    for (int j = 0; j < 4; j++) {
        int nn = ty + j * 8;
        float v = t[tx][nn];
        __nv_bfloat16 hi, lo; split_bf16(v, hi, lo);
        size_t ob = ((size_t)e * DIM + n0 + nn) * K2D + k0 + tx;
        g_w2b[ob] = hi; g_w2b[ob + HID] = lo;
    }
}

// ---------------- mma.sync grouped GEMMs --------------------------------------
// 128x128 block tile, 128 threads = 4 warps (2m x 2n), warp tile 64x64.
// 3-stage cp.async pipeline; logical K = 3x dedup width via per-chunk offsets.

#define LOADT(offA, offB, s) do {                                    \
    _Pragma("unroll") for (int i = 0; i < 8; i++)                    \
        CP16(Ab_[s] + dst[i], aptr[i] + (offA));                     \
    _Pragma("unroll") for (int i = 0; i < 8; i++)                    \
        CP16(Bb_[s] + dst[i], bptr[i] + (offB));                     \
    CP_COMMIT(); } while (0)

#define GEMM_CORE(NC, OFFA, OFFB)                                             \
    const int l = tid & 31, wid = tid >> 5;                                   \
    const int wm = (wid >> 1) * 64, wn = (wid & 1) * 64;                      \
    const int mA = (l & 7) | (((l >> 3) & 1) << 3);                           \
    const int khA = (l >> 4) & 1;                                             \
    const int nB = (l & 7) | (((l >> 4) & 1) << 3);                           \
    const int khB = (l >> 3) & 1;                                             \
    uint32_t aRow[4], bRow[4], kxA[4], kxB[4];                                \
    _Pragma("unroll") for (int mt = 0; mt < 4; mt++)                          \
        aRow[mt] = (wm + mt * 16 + mA) * 128;                                 \
    _Pragma("unroll") for (int jj = 0; jj < 4; jj++)                          \
        bRow[jj] = (wn + jj * 16 + nB) * 128;                                 \
    _Pragma("unroll") for (int ks = 0; ks < 4; ks++) {                        \
        kxA[ks] = ((uint32_t)(ks * 32 + khA * 16)) ^ (((uint32_t)(l & 7)) << 4); \
        kxB[ks] = ((uint32_t)(ks * 32 + khB * 16)) ^ (((uint32_t)(l & 7)) << 4); \
    }                                                                         \
    float acc[4][8][4];                                                       \
    _Pragma("unroll") for (int a = 0; a < 4; a++)                             \
    _Pragma("unroll") for (int b = 0; b < 8; b++)                             \
    _Pragma("unroll") for (int q = 0; q < 4; q++) acc[a][b][q] = 0.f;         \
    LOADT(OFFA(0), OFFB(0), 0);                                               \
    LOADT(OFFA(1), OFFB(1), 1);                                               \
    for (int c = 0; c < (NC); c++) {                                          \
        int s = c % 3;                                                        \
        if (c == (NC) - 1) CP_WAIT0(); else CP_WAIT1();                       \
        __syncthreads();                                                      \
        if (c + 2 < (NC)) { int s2 = (c + 2) % 3; LOADT(OFFA(c + 2), OFFB(c + 2), s2); } \
        uint32_t As = Ab_[s], Bs = Bb_[s];                                    \
        _Pragma("unroll") for (int ks = 0; ks < 4; ks++) {                    \
            uint32_t afr[4][4], bfr[4][4];                                    \
            _Pragma("unroll") for (int mt = 0; mt < 4; mt++)                  \
                ldsm4(afr[mt], As + aRow[mt] + kxA[ks]);                      \
            _Pragma("unroll") for (int jj = 0; jj < 4; jj++)                  \
                ldsm4(bfr[jj], Bs + bRow[jj] + kxB[ks]);                      \
            _Pragma("unroll") for (int mt = 0; mt < 4; mt++)                  \
            _Pragma("unroll") for (int jj = 0; jj < 4; jj++) {                \
                mma16816(acc[mt][2 * jj],     afr[mt], bfr[jj][0], bfr[jj][1]); \
                mma16816(acc[mt][2 * jj + 1], afr[mt], bfr[jj][2], bfr[jj][3]); \
            }                                                                 \
        }                                                                     \
    }

#define OFFA1(c) (((c) < 32 ? (c) : (c) - 32) * 128)
#define OFFB1(c) (((c) < 16 ? (c) : (c) - 16) * 128)
#define OFFA2(c) (((c) < 64 ? (c) : (c) - 64) * 128)
#define OFFB2(c) (((c) < 32 ? (c) : (c) - 32) * 128)

__global__ __launch_bounds__(128)
void gemm1_mma() {
    int e = blockIdx.z;
    int cnt = g_cnt[e];
    int row0 = blockIdx.y * 128;
    if (row0 >= cnt) return;
    int hcol0 = blockIdx.x * 64;

    extern __shared__ char sm[];
    uint32_t raw = smem_u32(sm);
    uint32_t base = (raw + 1023u) & ~1023u;
    char* smc = sm + (base - raw);
    int* sp = (int*)smc;
    uint32_t Ab_[3] = { base + 1024, base + 1024 + 32768, base + 1024 + 65536 };
    uint32_t Bb_[3] = { Ab_[0] + 16384, Ab_[1] + 16384, Ab_[2] + 16384 };

    int tid = threadIdx.x;
    sp[tid] = g_list[e * NTOK + min(row0 + tid, cnt - 1)];
    __syncthreads();

    // loader mapping: 128 threads x 16 cp.16B per chunk (8 A + 8 B)
    int seg = tid & 7, rb = tid >> 3;
    const char* w1e = (const char*)(g_w1b + (size_t)e * (2 * HID) * K1D);
    const char* aptr[8]; const char* bptr[8]; uint32_t dst[8];
#pragma unroll
    for (int i = 0; i < 8; i++) {
        int r = rb + 16 * i;
        dst[i] = SWZ(r * 128 + seg * 16);
        int tok = sp[r] >> 1;
        aptr[i] = (const char*)g_xb + (size_t)tok * K1D * 2 + seg * 16;
        int nrow = (r < 64) ? (hcol0 + r) : (HID + hcol0 + (r - 64));
        bptr[i] = w1e + (size_t)nrow * K1D * 2 + seg * 16;
    }

    GEMM_CORE(48, OFFA1, OFFB1)

    // epilogue: acc -> smem (stride 129) -> SwiGLU -> g_actb [hi|lo]
    __syncthreads();
    float* S = (float*)(smc + 1024);
#pragma unroll
    for (int mt = 0; mt < 4; mt++) {
        int r0 = wm + mt * 16 + (l >> 2);
#pragma unroll
        for (int j = 0; j < 8; j++) {
            int cN = wn + j * 8 + (l & 3) * 2;
            S[r0 * 129 + cN]     = acc[mt][j][0];
            S[r0 * 129 + cN + 1] = acc[mt][j][1];
            S[(r0 + 8) * 129 + cN]     = acc[mt][j][2];
            S[(r0 + 8) * 129 + cN + 1] = acc[mt][j][3];
        }
    }
    __syncthreads();
#pragma unroll
    for (int pass = 0; pass < 32; pass++) {
        int m = pass * 4 + wid;
        if (row0 + m < cnt) {
            int p = sp[m];
            __nv_bfloat16* ab = g_actb + (size_t)p * K2D;
#pragma unroll
            for (int u = 0; u < 2; u++) {
                int hh = l + u * 32;
                float gv = S[m * 129 + hh];
                float lv = S[m * 129 + 64 + hh];
                float v = (gv / (1.f + expf(-gv))) * lv;
                __nv_bfloat16 hi, lo; split_bf16(v, hi, lo);
                int h = hcol0 + hh;
                ab[h] = hi; ab[HID + h] = lo;
            }
        }
    }
}

__global__ __launch_bounds__(128)
void gemm2_mma() {
    int e = blockIdx.z;
    int cnt = g_cnt[e];
    int row0 = blockIdx.y * 128;
    if (row0 >= cnt) return;
    int n0 = blockIdx.x * 128;

    extern __shared__ char sm[];
    uint32_t raw = smem_u32(sm);
    uint32_t base = (raw + 1023u) & ~1023u;
    char* smc = sm + (base - raw);
    int* sp = (int*)smc;
    uint32_t Ab_[3] = { base + 1024, base + 1024 + 32768, base + 1024 + 65536 };
    uint32_t Bb_[3] = { Ab_[0] + 16384, Ab_[1] + 16384, Ab_[2] + 16384 };

    int tid = threadIdx.x;
    sp[tid] = g_list[e * NTOK + min(row0 + tid, cnt - 1)];
    __syncthreads();

    int seg = tid & 7, rb = tid >> 3;
    const char* w2e = (const char*)(g_w2b + (size_t)e * DIM * K2D);
    const char* aptr[8]; const char* bptr[8]; uint32_t dst[8];
#pragma unroll
    for (int i = 0; i < 8; i++) {
        int r = rb + 16 * i;
        dst[i] = SWZ(r * 128 + seg * 16);
        int p = sp[r];
        aptr[i] = (const char*)g_actb + (size_t)p * K2D * 2 + seg * 16;
        bptr[i] = w2e + (size_t)(n0 + r) * K2D * 2 + seg * 16;
    }

    GEMM_CORE(96, OFFA2, OFFB2)

    // epilogue: fragments straight to g_y
#pragma unroll
    for (int mt = 0; mt < 4; mt++) {
        int mloc = wm + mt * 16 + (l >> 2);
#pragma unroll
        for (int half = 0; half < 2; half++) {
            int m = mloc + half * 8;
            if (row0 + m < cnt) {
                int p = sp[m];
                float* yp = g_y + (size_t)p * DIM + n0 + wn + (l & 3) * 2;
#pragma unroll
                for (int j = 0; j < 8; j++) {
                    float2 v;
                    v.x = acc[mt][j][half * 2 + 0];
                    v.y = acc[mt][j][half * 2 + 1];
                    *(float2*)(yp + j * 8) = v;
                }
            }
        }
    }
}

// ---------------- combine ----------------------------------------------------
__global__ void combine_kernel(float* __restrict__ out) {
    int i = blockIdx.x * blockDim.x + threadIdx.x;
    if (i >= NTOK * DIM / 4) return;
    int n  = i / (DIM / 4);
    int c4 = (i % (DIM / 4)) * 4;
    float w0 = g_pw[2 * n];
    float w1 = g_pw[2 * n + 1];
    float4 y0 = *(const float4*)(g_y + (size_t)(2 * n) * DIM + c4);
    float4 y1 = *(const float4*)(g_y + (size_t)(2 * n + 1) * DIM + c4);
    float4 o;
    o.x = w0 * y0.x + w1 * y1.x;
    o.y = w0 * y0.y + w1 * y1.y;
    o.z = w0 * y0.z + w1 * y1.z;
    o.w = w0 * y0.w + w1 * y1.w;
    *(float4*)(out + (size_t)n * DIM + c4) = o;
}

// ---------------- launch -----------------------------------------------------
extern "C" void kernel_launch(void* const* d_in, const int* in_sizes, int n_in,
                              void* d_out, int out_size) {
    const float* x  = (const float*)d_in[0];
    const float* gw = (const float*)d_in[1];
    const float* w1 = (const float*)d_in[2];
    const float* w2 = (const float*)d_in[3];
    float* out    = (float*)d_out;
    float* logits = out + (size_t)NTOK * DIM;

    cudaFuncSetAttribute(gemm1_mma, cudaFuncAttributeMaxDynamicSharedMemorySize, SMEM_BYTES);
    cudaFuncSetAttribute(gemm2_mma, cudaFuncAttributeMaxDynamicSharedMemorySize, SMEM_BYTES);

    init_kernel<<<1, 32>>>();
    router_kernel<<<NTOK / 8, 256>>>(x, gw, logits);

    convert_x_kernel<<<(NTOK * DIM / 4 + 255) / 256, 256>>>(x);
    convert_w1_kernel<<<dim3(2 * HID / 32, DIM / 32, NEXP), dim3(32, 8)>>>(w1);
    convert_w2_kernel<<<dim3(DIM / 32, HID / 32, NEXP), dim3(32, 8)>>>(w2);

    gemm1_mma<<<dim3(HID / 64, NTOK / 128, NEXP), 128, SMEM_BYTES>>>();
    gemm2_mma<<<dim3(DIM / 128, NTOK / 128, NEXP), 128, SMEM_BYTES>>>();

    combine_kernel<<<(NTOK * DIM / 4 + 255) / 256, 256>>>(out);
}